// round 6
// baseline (speedup 1.0000x reference)
#include <cuda_runtime.h>
#include <cuda_bf16.h>

#define EMB       512
#define N_NODES   16384
#define N_PAIRS   200000
#define NBLK      148
#define NTHR      1024

// Scratch (device globals — no allocation allowed)
__device__ float  g_node_mean[N_NODES];
__device__ __align__(16) float2 g_pair[N_PAIRS];   // x = event-sum, y = count
__device__ __align__(16) float2 g_place[N_NODES];  // x = pair-mean sum, y = pair count
__device__ unsigned g_cnt = 0;     // barrier arrivals (reset by last arriver)
__device__ unsigned g_sense = 0;   // monotonic epoch (never reset; replay-safe)

// Vectorized float2 reduction (one L2 atomic op for sum+count)
__device__ __forceinline__ void red_add_v2(float2* addr, float a, float b) {
    asm volatile("red.global.add.v2.f32 [%0], {%1, %2};"
                 :: "l"(addr), "f"(a), "f"(b) : "memory");
}

// Grid-wide barrier. Correct only because all gridDim.x blocks are co-resident
// (148 blocks, 1/SM). Cumulative release/acquire via __threadfence.
__device__ __forceinline__ void grid_barrier() {
    __syncthreads();
    if (threadIdx.x == 0) {
        volatile unsigned* vs = &g_sense;
        unsigned s = *vs;                 // read epoch BEFORE arriving
        __threadfence();                  // release this block's writes
        unsigned v = atomicAdd(&g_cnt, 1);
        if (v == gridDim.x - 1) {
            g_cnt = 0;                    // reset for next barrier/replay
            __threadfence();
            atomicAdd(&g_sense, 1);       // release epoch bump
        } else {
            while (*vs == s) __nanosleep(64);
        }
        __threadfence();                  // acquire
    }
    __syncthreads();
}

__global__ void __launch_bounds__(NTHR, 1)
k_fused(const float* __restrict__ emb,
        const int* __restrict__ pair_place,
        const int* __restrict__ event_pair,
        const int* __restrict__ event_src,
        const int* __restrict__ event_ndst,
        const int* __restrict__ dst_event,
        const int* __restrict__ dst_node,
        float* __restrict__ out,
        int n_events, int n_dst) {
    extern __shared__ float s_nm[];       // 64KB node_mean table
    const int tid = blockIdx.x * NTHR + threadIdx.x;
    const int stride = NBLK * NTHR;       // 151552
    const int warp = tid >> 5, lane = tid & 31;
    const int n_warps = stride >> 5;      // 4736

    // ---------------- Phase A: zero accumulators + node_mean ----------------
    {
        float4 z = make_float4(0.f, 0.f, 0.f, 0.f);
        float4* gp = reinterpret_cast<float4*>(g_pair);    // 100000 float4
        for (int j = tid; j < N_PAIRS / 2; j += stride) gp[j] = z;
        float4* gl = reinterpret_cast<float4*>(g_place);   // 8192 float4
        for (int j = tid; j < N_NODES / 2; j += stride) gl[j] = z;

        for (int row = warp; row < N_NODES; row += n_warps) {
            const float4* r = reinterpret_cast<const float4*>(emb + (size_t)row * EMB);
            float s = 0.0f;
            #pragma unroll
            for (int k = 0; k < 4; k++) {
                float4 v = r[lane + 32 * k];
                s += (v.x + v.y) + (v.z + v.w);
            }
            #pragma unroll
            for (int o = 16; o > 0; o >>= 1)
                s += __shfl_down_sync(0xffffffffu, s, o);
            if (lane == 0)
                g_node_mean[row] = s * (1.0f / EMB);
        }
    }
    grid_barrier();

    // ---------------- Phase B: stage table + scatter ----------------
    {
        const float4* src = reinterpret_cast<const float4*>(g_node_mean);
        float4* dst = reinterpret_cast<float4*>(s_nm);
        #pragma unroll
        for (int k = 0; k < N_NODES / 4 / NTHR; k++)
            dst[threadIdx.x + NTHR * k] = src[threadIdx.x + NTHR * k];
        __syncthreads();

        // events: one red.v2 each (sum of nm[src], count)
        for (int e = tid; e < n_events; e += stride) {
            int p = event_pair[e];
            red_add_v2(&g_pair[p], s_nm[event_src[e]], 1.0f);
        }
        // dst entries: dst_event sorted -> monotonic gathers; scalar atomic each
        for (int i = tid; i < n_dst; i += stride) {
            int e = __ldg(&dst_event[i]);
            int p = __ldg(&event_pair[e]);
            float nd = (float)__ldg(&event_ndst[e]);
            atomicAdd(&g_pair[p].x, s_nm[__ldg(&dst_node[i])] / (nd + 1.0f));
        }
    }
    grid_barrier();

    // ---------------- Phase C: pair -> place (2 pairs/thread) ----------------
    for (int t = tid; t < N_PAIRS / 2; t += stride) {
        float4 a = reinterpret_cast<const float4*>(g_pair)[t];
        int2 pl = reinterpret_cast<const int2*>(pair_place)[t];
        if (a.y > 0.0f)
            red_add_v2(&g_place[pl.x], (a.x / a.y + s_nm[pl.x]) * (1.0f / 3.0f), 1.0f);
        if (a.w > 0.0f)
            red_add_v2(&g_place[pl.y], (a.z / a.w + s_nm[pl.y]) * (1.0f / 3.0f), 1.0f);
    }
    grid_barrier();

    // ---------------- Phase D: broadcast fill (store-cap bound) ----------------
    for (int row = warp; row < N_NODES; row += n_warps) {
        float2 a = g_place[row];
        float v = (a.y > 0.0f) ? (a.x / a.y) : 0.0f;
        float4 v4 = make_float4(v, v, v, v);
        float4* o = reinterpret_cast<float4*>(out + (size_t)row * (3 * EMB));
        #pragma unroll
        for (int k = 0; k < 12; k++)
            o[lane + 32 * k] = v4;
    }
}

// ---------------------------------------------------------------------------
extern "C" void kernel_launch(void* const* d_in, const int* in_sizes, int n_in,
                              void* d_out, int out_size) {
    const float* embeddings = (const float*)d_in[0];
    const int* pair_place   = (const int*)d_in[1];
    const int* event_pair   = (const int*)d_in[2];
    const int* event_src    = (const int*)d_in[3];
    const int* event_ndst   = (const int*)d_in[4];
    const int* dst_event    = (const int*)d_in[5];
    const int* dst_node     = (const int*)d_in[6];
    float* out = (float*)d_out;

    int n_events = in_sizes[2];
    int n_dst = in_sizes[5];

    const int SMEM = N_NODES * (int)sizeof(float);   // 64KB
    cudaFuncSetAttribute(k_fused,
                         cudaFuncAttributeMaxDynamicSharedMemorySize, SMEM);

    k_fused<<<NBLK, NTHR, SMEM>>>(embeddings, pair_place, event_pair, event_src,
                                  event_ndst, dst_event, dst_node, out,
                                  n_events, n_dst);
}

// round 7
// speedup vs baseline: 1.3847x; 1.3847x over previous
#include <cuda_runtime.h>
#include <cuda_bf16.h>

#define EMB       512
#define N_NODES   16384
#define N_PAIRS   200000
#define MAX_EVENTS 1000000
#define SC_BLK    296
#define SC_THR    1024

// Scratch (device globals — no allocation allowed)
__device__ float  g_node_mean[N_NODES];
__device__ __align__(16) float2 g_pair[N_PAIRS];    // x = event-sum, y = count
__device__ __align__(16) float2 g_place[N_NODES];   // x = pair-mean sum, y = count
__device__ __align__(16) int    g_evt_off[MAX_EVENTS];
__device__ unsigned g_cnt = 0;     // barrier arrivals (reset by last arriver)
__device__ unsigned g_sense = 0;   // monotonic epoch (never reset; replay-safe)

// Vectorized float2 reduction (one L2 atomic op for sum+count)
__device__ __forceinline__ void red_add_v2(float2* addr, float a, float b) {
    asm volatile("red.global.add.v2.f32 [%0], {%1, %2};"
                 :: "l"(addr), "f"(a), "f"(b) : "memory");
}

// Grid barrier across SC_BLK co-resident blocks (2/SM guaranteed by smem+regs).
__device__ __forceinline__ void grid_barrier() {
    __syncthreads();
    if (threadIdx.x == 0) {
        volatile unsigned* vs = &g_sense;
        unsigned s = *vs;                 // read epoch BEFORE arriving
        __threadfence();                  // release
        unsigned v = atomicAdd(&g_cnt, 1);
        if (v == gridDim.x - 1) {
            g_cnt = 0;
            __threadfence();
            atomicAdd(&g_sense, 1);       // release epoch bump
        } else {
            while (*vs == s) __nanosleep(32);
        }
        __threadfence();                  // acquire
    }
    __syncthreads();
}

// ---------------------------------------------------------------------------
// K1 (fused, independent work): zero accumulators; node_mean (warp/row);
// evt_off boundary scan (dst_event sorted; int4).    grid = 2048 x 256
// ---------------------------------------------------------------------------
__global__ void k_prep(const float* __restrict__ emb,
                       const int* __restrict__ dst_event,
                       int n_dst) {
    int tid = blockIdx.x * blockDim.x + threadIdx.x;
    int stride = gridDim.x * blockDim.x;

    float4 z = make_float4(0.f, 0.f, 0.f, 0.f);
    float4* gp = reinterpret_cast<float4*>(g_pair);
    for (int j = tid; j < N_PAIRS / 2; j += stride) gp[j] = z;
    float4* gl = reinterpret_cast<float4*>(g_place);
    for (int j = tid; j < N_NODES / 2; j += stride) gl[j] = z;

    int n_grp = (n_dst + 3) >> 2;
    const int4* de4 = reinterpret_cast<const int4*>(dst_event);
    for (int g = tid; g < n_grp; g += stride) {
        int base = g << 2;
        if (base + 3 < n_dst) {
            int4 v = de4[g];
            int prev = (base == 0) ? -1 : __ldg(&dst_event[base - 1]);
            if (v.x != prev) g_evt_off[v.x] = base;
            if (v.y != v.x)  g_evt_off[v.y] = base + 1;
            if (v.z != v.y)  g_evt_off[v.z] = base + 2;
            if (v.w != v.z)  g_evt_off[v.w] = base + 3;
        } else {
            for (int i = base; i < n_dst; i++) {
                int e = dst_event[i];
                int prev = (i == 0) ? -1 : dst_event[i - 1];
                if (e != prev) g_evt_off[e] = i;
            }
        }
    }

    int row = tid >> 5;
    int lane = tid & 31;
    const float4* r = reinterpret_cast<const float4*>(emb + (size_t)row * EMB);
    float s = 0.0f;
    #pragma unroll
    for (int k = 0; k < 4; k++) {
        float4 v = r[lane + 32 * k];
        s += (v.x + v.y) + (v.z + v.w);
    }
    #pragma unroll
    for (int off = 16; off > 0; off >>= 1)
        s += __shfl_down_sync(0xffffffffu, s, off);
    if (lane == 0)
        g_node_mean[row] = s * (1.0f / EMB);
}

// ---------------------------------------------------------------------------
// K2: scatter (4 events/thread, int4 index loads) + grid barrier + pair->place.
//   296 blocks x 1024 thr, 64KB smem (node_mean table), 2 blocks/SM.
// ---------------------------------------------------------------------------
__global__ void __launch_bounds__(SC_THR, 2)
k_scatter_p2p(const int* __restrict__ event_pair,
              const int* __restrict__ event_src,
              const int* __restrict__ event_ndst,
              const int* __restrict__ dst_node,
              const int* __restrict__ pair_place,
              int n_events) {
    extern __shared__ float s_nm[];   // 64KB
    {
        const float4* src = reinterpret_cast<const float4*>(g_node_mean);
        float4* dst = reinterpret_cast<float4*>(s_nm);
        #pragma unroll
        for (int k = 0; k < N_NODES / 4 / SC_THR; k++)
            dst[threadIdx.x + SC_THR * k] = src[threadIdx.x + SC_THR * k];
    }
    __syncthreads();

    const int tid = blockIdx.x * SC_THR + threadIdx.x;
    const int stride = SC_BLK * SC_THR;

    // ---- events, 4 per thread via int4 ----
    int n_vec = n_events >> 2;
    const int4* ep4 = reinterpret_cast<const int4*>(event_pair);
    const int4* es4 = reinterpret_cast<const int4*>(event_src);
    const int4* en4 = reinterpret_cast<const int4*>(event_ndst);
    const int4* eo4 = reinterpret_cast<const int4*>(g_evt_off);
    for (int t = tid; t < n_vec; t += stride) {
        int4 p  = ep4[t];
        int4 sI = es4[t];
        int4 nd = en4[t];
        int4 of = eo4[t];
        int pa[4]  = {p.x, p.y, p.z, p.w};
        int sa[4]  = {sI.x, sI.y, sI.z, sI.w};
        int nda[4] = {nd.x, nd.y, nd.z, nd.w};
        int ofa[4] = {of.x, of.y, of.z, of.w};
        #pragma unroll
        for (int q = 0; q < 4; q++) {
            float dsum = 0.0f;
            #pragma unroll
            for (int j = 0; j < 4; j++) {
                float v = (j < nda[q]) ? s_nm[__ldg(&dst_node[ofa[q] + j])] : 0.0f;
                dsum += v;
            }
            float val = s_nm[sa[q]] + dsum / ((float)nda[q] + 1.0f);
            red_add_v2(&g_pair[pa[q]], val, 1.0f);
        }
    }
    // scalar tail
    for (int e = (n_vec << 2) + tid; e < n_events; e += stride) {
        int p = event_pair[e], nd = event_ndst[e], off = g_evt_off[e];
        float dsum = 0.0f;
        #pragma unroll
        for (int j = 0; j < 4; j++)
            dsum += (j < nd) ? s_nm[__ldg(&dst_node[off + j])] : 0.0f;
        red_add_v2(&g_pair[p], s_nm[event_src[e]] + dsum / ((float)nd + 1.0f), 1.0f);
    }

    grid_barrier();

    // ---- pair -> place (2 pairs/thread), reusing staged table ----
    for (int t = tid; t < N_PAIRS / 2; t += stride) {
        float4 a = reinterpret_cast<const float4*>(g_pair)[t];
        int2 pl = reinterpret_cast<const int2*>(pair_place)[t];
        if (a.y > 0.0f)
            red_add_v2(&g_place[pl.x], (a.x / a.y + s_nm[pl.x]) * (1.0f / 3.0f), 1.0f);
        if (a.w > 0.0f)
            red_add_v2(&g_place[pl.y], (a.z / a.w + s_nm[pl.y]) * (1.0f / 3.0f), 1.0f);
    }
}

// ---------------------------------------------------------------------------
// K3: broadcast fill — one warp per row, 12 independent STG.128 per lane.
//     At the chip store-path cap (~6.1TB/s); this is the floor.
// ---------------------------------------------------------------------------
__global__ void k_fill_out(float* __restrict__ out) {
    int tid = blockIdx.x * blockDim.x + threadIdx.x;
    int row = tid >> 5;
    int lane = tid & 31;
    float2 a = g_place[row];
    float v = (a.y > 0.0f) ? (a.x / a.y) : 0.0f;
    float4 v4 = make_float4(v, v, v, v);
    float4* o = reinterpret_cast<float4*>(out + (size_t)row * (3 * EMB));
    #pragma unroll
    for (int k = 0; k < 12; k++)
        o[lane + 32 * k] = v4;
}

// ---------------------------------------------------------------------------
extern "C" void kernel_launch(void* const* d_in, const int* in_sizes, int n_in,
                              void* d_out, int out_size) {
    const float* embeddings = (const float*)d_in[0];
    const int* pair_place   = (const int*)d_in[1];
    const int* event_pair   = (const int*)d_in[2];
    const int* event_src    = (const int*)d_in[3];
    const int* event_ndst   = (const int*)d_in[4];
    const int* dst_event    = (const int*)d_in[5];
    const int* dst_node     = (const int*)d_in[6];
    float* out = (float*)d_out;

    int n_events = in_sizes[2];
    int n_dst = in_sizes[5];

    const int SMEM = N_NODES * (int)sizeof(float);   // 64KB
    cudaFuncSetAttribute(k_scatter_p2p,
                         cudaFuncAttributeMaxDynamicSharedMemorySize, SMEM);

    k_prep<<<2048, 256>>>(embeddings, dst_event, n_dst);
    k_scatter_p2p<<<SC_BLK, SC_THR, SMEM>>>(event_pair, event_src, event_ndst,
                                            dst_node, pair_place, n_events);
    k_fill_out<<<2048, 256>>>(out);
}

// round 8
// speedup vs baseline: 1.4459x; 1.0442x over previous
#include <cuda_runtime.h>
#include <cuda_bf16.h>

#define EMB       512
#define N_NODES   16384
#define N_PAIRS   200000
#define MAX_EVENTS 1000000
#define SC_BLK    444
#define SC_THR    512

// Scratch (device globals — no allocation allowed)
__device__ float  g_node_mean[N_NODES];
__device__ __align__(16) float2 g_pair[N_PAIRS];    // x = event-sum, y = count
__device__ __align__(16) float2 g_place[N_NODES];   // x = pair-mean sum, y = count
__device__ __align__(16) int    g_evt_off[MAX_EVENTS];
__device__ unsigned g_cnt = 0;     // barrier arrivals (reset by last arriver)
__device__ unsigned g_sense = 0;   // monotonic epoch (never reset; replay-safe)

// Vectorized float2 reduction (one L2 atomic op for sum+count)
__device__ __forceinline__ void red_add_v2(float2* addr, float a, float b) {
    asm volatile("red.global.add.v2.f32 [%0], {%1, %2};"
                 :: "l"(addr), "f"(a), "f"(b) : "memory");
}

// Grid barrier across SC_BLK co-resident blocks (3/SM guaranteed: 3x64KB smem).
__device__ __forceinline__ void grid_barrier() {
    __syncthreads();
    if (threadIdx.x == 0) {
        volatile unsigned* vs = &g_sense;
        unsigned s = *vs;                 // read epoch BEFORE arriving
        __threadfence();                  // release
        unsigned v = atomicAdd(&g_cnt, 1);
        if (v == gridDim.x - 1) {
            g_cnt = 0;
            __threadfence();
            atomicAdd(&g_sense, 1);       // release epoch bump
        } else {
            while (*vs == s) __nanosleep(32);
        }
        __threadfence();                  // acquire
    }
    __syncthreads();
}

// ---------------------------------------------------------------------------
// K1 (fused, independent work): zero accumulators; node_mean (warp/row);
// evt_off boundary scan (dst_event sorted; int4).    grid = 2048 x 256
// (~74MB of reads; measured at its bandwidth floor — do not touch)
// ---------------------------------------------------------------------------
__global__ void k_prep(const float* __restrict__ emb,
                       const int* __restrict__ dst_event,
                       int n_dst) {
    int tid = blockIdx.x * blockDim.x + threadIdx.x;
    int stride = gridDim.x * blockDim.x;

    float4 z = make_float4(0.f, 0.f, 0.f, 0.f);
    float4* gp = reinterpret_cast<float4*>(g_pair);
    for (int j = tid; j < N_PAIRS / 2; j += stride) gp[j] = z;
    float4* gl = reinterpret_cast<float4*>(g_place);
    for (int j = tid; j < N_NODES / 2; j += stride) gl[j] = z;

    int n_grp = (n_dst + 3) >> 2;
    const int4* de4 = reinterpret_cast<const int4*>(dst_event);
    for (int g = tid; g < n_grp; g += stride) {
        int base = g << 2;
        if (base + 3 < n_dst) {
            int4 v = de4[g];
            int prev = (base == 0) ? -1 : __ldg(&dst_event[base - 1]);
            if (v.x != prev) g_evt_off[v.x] = base;
            if (v.y != v.x)  g_evt_off[v.y] = base + 1;
            if (v.z != v.y)  g_evt_off[v.z] = base + 2;
            if (v.w != v.z)  g_evt_off[v.w] = base + 3;
        } else {
            for (int i = base; i < n_dst; i++) {
                int e = dst_event[i];
                int prev = (i == 0) ? -1 : dst_event[i - 1];
                if (e != prev) g_evt_off[e] = i;
            }
        }
    }

    int row = tid >> 5;
    int lane = tid & 31;
    const float4* r = reinterpret_cast<const float4*>(emb + (size_t)row * EMB);
    float s = 0.0f;
    #pragma unroll
    for (int k = 0; k < 4; k++) {
        float4 v = r[lane + 32 * k];
        s += (v.x + v.y) + (v.z + v.w);
    }
    #pragma unroll
    for (int off = 16; off > 0; off >>= 1)
        s += __shfl_down_sync(0xffffffffu, s, off);
    if (lane == 0)
        g_node_mean[row] = s * (1.0f / EMB);
}

// ---------------------------------------------------------------------------
// K2: scatter (scalar, R5-proven) + grid barrier + pair->place.
//   444 blocks x 512 thr, 64KB smem node_mean table, 3 blocks/SM co-resident.
// ---------------------------------------------------------------------------
__global__ void __launch_bounds__(SC_THR, 3)
k_scatter_p2p(const int* __restrict__ event_pair,
              const int* __restrict__ event_src,
              const int* __restrict__ event_ndst,
              const int* __restrict__ dst_node,
              const int* __restrict__ pair_place,
              int n_events) {
    extern __shared__ float s_nm[];   // 64KB
    {
        const float4* src = reinterpret_cast<const float4*>(g_node_mean);
        float4* dst = reinterpret_cast<float4*>(s_nm);
        int t = threadIdx.x;
        #pragma unroll
        for (int k = 0; k < N_NODES / 4 / SC_THR; k++)
            dst[t + SC_THR * k] = src[t + SC_THR * k];
    }
    __syncthreads();

    const int tid = blockIdx.x * SC_THR + threadIdx.x;
    const int stride = SC_BLK * SC_THR;

    for (int e = tid; e < n_events; e += stride) {
        int p   = event_pair[e];
        int nd  = event_ndst[e];
        int off = g_evt_off[e];

        // nd in [1,4]: predicated fixed-trip loop, independent smem gathers
        float dsum = 0.0f;
        #pragma unroll
        for (int j = 0; j < 4; j++) {
            float v = (j < nd) ? s_nm[__ldg(&dst_node[off + j])] : 0.0f;
            dsum += v;
        }

        float val = s_nm[event_src[e]] + dsum / ((float)nd + 1.0f);
        red_add_v2(&g_pair[p], val, 1.0f);
    }

    grid_barrier();

    // ---- pair -> place (2 pairs/thread), reusing staged smem table ----
    for (int t = tid; t < N_PAIRS / 2; t += stride) {
        float4 a = reinterpret_cast<const float4*>(g_pair)[t];
        int2 pl = reinterpret_cast<const int2*>(pair_place)[t];
        if (a.y > 0.0f)
            red_add_v2(&g_place[pl.x], (a.x / a.y + s_nm[pl.x]) * (1.0f / 3.0f), 1.0f);
        if (a.w > 0.0f)
            red_add_v2(&g_place[pl.y], (a.z / a.w + s_nm[pl.y]) * (1.0f / 3.0f), 1.0f);
    }
}

// ---------------------------------------------------------------------------
// K3: broadcast fill — one warp per row, 12 independent STG.128 per lane.
//     At the chip store-path cap (~6.1TB/s); this is the floor.
// ---------------------------------------------------------------------------
__global__ void k_fill_out(float* __restrict__ out) {
    int tid = blockIdx.x * blockDim.x + threadIdx.x;
    int row = tid >> 5;
    int lane = tid & 31;
    float2 a = g_place[row];
    float v = (a.y > 0.0f) ? (a.x / a.y) : 0.0f;
    float4 v4 = make_float4(v, v, v, v);
    float4* o = reinterpret_cast<float4*>(out + (size_t)row * (3 * EMB));
    #pragma unroll
    for (int k = 0; k < 12; k++)
        o[lane + 32 * k] = v4;
}

// ---------------------------------------------------------------------------
extern "C" void kernel_launch(void* const* d_in, const int* in_sizes, int n_in,
                              void* d_out, int out_size) {
    const float* embeddings = (const float*)d_in[0];
    const int* pair_place   = (const int*)d_in[1];
    const int* event_pair   = (const int*)d_in[2];
    const int* event_src    = (const int*)d_in[3];
    const int* event_ndst   = (const int*)d_in[4];
    const int* dst_event    = (const int*)d_in[5];
    const int* dst_node     = (const int*)d_in[6];
    float* out = (float*)d_out;

    int n_events = in_sizes[2];
    int n_dst = in_sizes[5];

    const int SMEM = N_NODES * (int)sizeof(float);   // 64KB
    cudaFuncSetAttribute(k_scatter_p2p,
                         cudaFuncAttributeMaxDynamicSharedMemorySize, SMEM);

    k_prep<<<2048, 256>>>(embeddings, dst_event, n_dst);
    k_scatter_p2p<<<SC_BLK, SC_THR, SMEM>>>(event_pair, event_src, event_ndst,
                                            dst_node, pair_place, n_events);
    k_fill_out<<<2048, 256>>>(out);
}